// round 1
// baseline (speedup 1.0000x reference)
#include <cuda_runtime.h>

#define BB 4
#define NF 128
#define NK 64
#define NV 64
#define LL 4096

#define TQ 64      // query tile per CTA
#define TL 32      // field tile per iteration
#define WP (TQ+4)  // padded row for w tile (272B, 16B-aligned rows)
#define FVP (NV+4) // padded row for transposed fvals tile

// Scratch: projection outputs, k-major [B][K][L]
__device__ float g_fkeys[BB*NK*LL];
__device__ float g_fvals[BB*NV*LL];
__device__ float g_hkeys[BB*NK*LL];

// ---------------------------------------------------------------------------
// Kernel A: 1x1-conv projections.  out[b,k,l] = sum_c W[k,c]*X[b,c,l] + bias[k]
// blockIdx.z selects which projection (0: fkeys, 1: fvals, 2: hkeys).
// ---------------------------------------------------------------------------
__global__ __launch_bounds__(256) void proj_kernel(
    const float* __restrict__ field, const float* __restrict__ query,
    const float* __restrict__ W_fk, const float* __restrict__ b_fk,
    const float* __restrict__ W_fv, const float* __restrict__ b_fv,
    const float* __restrict__ W_qk, const float* __restrict__ b_qk)
{
    const float *W, *bias, *X;
    float* out;
    switch (blockIdx.z) {
        case 0:  W = W_fk; bias = b_fk; X = field; out = g_fkeys; break;
        case 1:  W = W_fv; bias = b_fv; X = field; out = g_fvals; break;
        default: W = W_qk; bias = b_qk; X = query; out = g_hkeys; break;
    }

    __shared__ float Ws[NK*NF];
    __shared__ float bs[NK];
    for (int i = threadIdx.x; i < NK*NF; i += 256) Ws[i] = W[i];
    if (threadIdx.x < NK) bs[threadIdx.x] = bias[threadIdx.x];
    __syncthreads();

    const int b = blockIdx.y;
    const int l = blockIdx.x * 256 + threadIdx.x;
    const float* x = X + (size_t)b * NF * LL + l;

    float acc[NK];
    #pragma unroll
    for (int k = 0; k < NK; k++) acc[k] = bs[k];

    #pragma unroll 4
    for (int c = 0; c < NF; c++) {
        float xv = x[(size_t)c * LL];            // coalesced across lanes
        #pragma unroll
        for (int k = 0; k < NK; k++)
            acc[k] = fmaf(Ws[k*NF + c], xv, acc[k]);  // smem broadcast
    }

    float* o = out + (size_t)b * NK * LL + l;
    #pragma unroll
    for (int k = 0; k < NK; k++) o[(size_t)k * LL] = acc[k];
}

// ---------------------------------------------------------------------------
// Kernel B: fused "attention".
//   z[l,q]   = (1/8) * sum_k fkeys[k,l]*hkeys[k,q]
//   w        = exp(clip(z,-30,30))           (no online max needed: e^30 safe)
//   den[q]   = sum_l w[l,q] + 1e-16
//   y[v,q]   = (sum_l fvals[v,l]*w[l,q]) / den[q]
// One CTA per (batch, 64-query tile). 256 threads.
//   stage 1: thread (gt=tid/16, qt=tid%16) computes z for l in {2gt,2gt+1},
//            q in {4qt..4qt+3}; writes w to smem, keeps denom partials in regs.
//   stage 2: thread owns v in {4gt..4gt+3}, same q; rank-1 accumulate 4x4 tile.
// ---------------------------------------------------------------------------
__global__ __launch_bounds__(256) void attn_kernel(float* __restrict__ out)
{
    __shared__ float hk_s[NK][TQ];    // 16 KB
    __shared__ float fk_s[NK][TL];    //  8 KB
    __shared__ float fvT_s[TL][FVP];  // 8.5 KB (transposed: row l, col v)
    __shared__ float w_s[TL][WP];     // 8.5 KB
    __shared__ float dn_s[16][TQ];    //  4 KB

    const int tid = threadIdx.x;
    const int b   = blockIdx.y;
    const int qt  = tid & 15;   // 0..15
    const int gt  = tid >> 4;   // 0..15
    const int q0  = qt * 4;
    const int l0  = gt * 2;
    const int v0  = gt * 4;
    const int qbase = blockIdx.x * TQ;

    const float* fk_g = g_fkeys + (size_t)b * NK * LL;
    const float* fv_g = g_fvals + (size_t)b * NV * LL;
    const float* hk_g = g_hkeys + (size_t)b * NK * LL;

    // Load hkeys tile once: hk_s[k][q]
    for (int i = tid; i < NK*TQ; i += 256) {
        int k = i >> 6, q = i & 63;
        hk_s[k][q] = hk_g[(size_t)k * LL + qbase + q];
    }

    float acc[4][4];
    #pragma unroll
    for (int i = 0; i < 4; i++)
        #pragma unroll
        for (int j = 0; j < 4; j++) acc[i][j] = 0.f;
    float dnp[4] = {0.f, 0.f, 0.f, 0.f};

    for (int lt = 0; lt < LL; lt += TL) {
        // Load fkeys tile [NK][TL] and fvals tile transposed [TL][NV]
        for (int i = tid; i < NK*TL; i += 256) {
            int k = i >> 5, l = i & 31;
            fk_s[k][l] = fk_g[(size_t)k * LL + lt + l];
        }
        for (int i = tid; i < NV*TL; i += 256) {
            int v = i >> 5, l = i & 31;
            fvT_s[l][v] = fv_g[(size_t)v * LL + lt + l];  // coalesced read
        }
        __syncthreads();

        // ---- stage 1: z = fkeys^T hkeys ; w = exp(clip(z/8)) ----
        float z[2][4];
        #pragma unroll
        for (int i = 0; i < 2; i++)
            #pragma unroll
            for (int j = 0; j < 4; j++) z[i][j] = 0.f;

        #pragma unroll
        for (int k = 0; k < NK; k++) {
            float2 a = *(const float2*)&fk_s[k][l0];
            float4 h = *(const float4*)&hk_s[k][q0];
            z[0][0] = fmaf(a.x, h.x, z[0][0]);
            z[0][1] = fmaf(a.x, h.y, z[0][1]);
            z[0][2] = fmaf(a.x, h.z, z[0][2]);
            z[0][3] = fmaf(a.x, h.w, z[0][3]);
            z[1][0] = fmaf(a.y, h.x, z[1][0]);
            z[1][1] = fmaf(a.y, h.y, z[1][1]);
            z[1][2] = fmaf(a.y, h.z, z[1][2]);
            z[1][3] = fmaf(a.y, h.w, z[1][3]);
        }

        #pragma unroll
        for (int i = 0; i < 2; i++) {
            float4 wv;
            wv.x = __expf(fminf(fmaxf(z[i][0]*0.125f, -30.f), 30.f));
            wv.y = __expf(fminf(fmaxf(z[i][1]*0.125f, -30.f), 30.f));
            wv.z = __expf(fminf(fmaxf(z[i][2]*0.125f, -30.f), 30.f));
            wv.w = __expf(fminf(fmaxf(z[i][3]*0.125f, -30.f), 30.f));
            *(float4*)&w_s[l0 + i][q0] = wv;
            dnp[0] += wv.x; dnp[1] += wv.y; dnp[2] += wv.z; dnp[3] += wv.w;
        }
        __syncthreads();

        // ---- stage 2: acc[v][q] += fvals[v][l] * w[l][q] ----
        #pragma unroll 8
        for (int l = 0; l < TL; l++) {
            float4 fv = *(const float4*)&fvT_s[l][v0];
            float4 wv = *(const float4*)&w_s[l][q0];
            acc[0][0] = fmaf(fv.x, wv.x, acc[0][0]);
            acc[0][1] = fmaf(fv.x, wv.y, acc[0][1]);
            acc[0][2] = fmaf(fv.x, wv.z, acc[0][2]);
            acc[0][3] = fmaf(fv.x, wv.w, acc[0][3]);
            acc[1][0] = fmaf(fv.y, wv.x, acc[1][0]);
            acc[1][1] = fmaf(fv.y, wv.y, acc[1][1]);
            acc[1][2] = fmaf(fv.y, wv.z, acc[1][2]);
            acc[1][3] = fmaf(fv.y, wv.w, acc[1][3]);
            acc[2][0] = fmaf(fv.z, wv.x, acc[2][0]);
            acc[2][1] = fmaf(fv.z, wv.y, acc[2][1]);
            acc[2][2] = fmaf(fv.z, wv.z, acc[2][2]);
            acc[2][3] = fmaf(fv.z, wv.w, acc[2][3]);
            acc[3][0] = fmaf(fv.w, wv.x, acc[3][0]);
            acc[3][1] = fmaf(fv.w, wv.y, acc[3][1]);
            acc[3][2] = fmaf(fv.w, wv.z, acc[3][2]);
            acc[3][3] = fmaf(fv.w, wv.w, acc[3][3]);
        }
        __syncthreads();   // before next tile overwrites fk/fvT/w
    }

    // ---- denominator reduction across the 16 l-groups ----
    *(float4*)&dn_s[gt][q0] = *(float4*)dnp;
    __syncthreads();

    float den[4];
    #pragma unroll
    for (int j = 0; j < 4; j++) den[j] = 1e-16f;
    #pragma unroll
    for (int g = 0; g < 16; g++) {
        float4 d = *(const float4*)&dn_s[g][q0];
        den[0] += d.x; den[1] += d.y; den[2] += d.z; den[3] += d.w;
    }

    // ---- write y[b, v0..v0+3, qbase+q0..+3] ----
    #pragma unroll
    for (int i = 0; i < 4; i++) {
        float4 r;
        r.x = acc[i][0] / den[0];
        r.y = acc[i][1] / den[1];
        r.z = acc[i][2] / den[2];
        r.w = acc[i][3] / den[3];
        *(float4*)&out[((size_t)b * NV + v0 + i) * LL + qbase + q0] = r;
    }
}

// ---------------------------------------------------------------------------
extern "C" void kernel_launch(void* const* d_in, const int* in_sizes, int n_in,
                              void* d_out, int out_size)
{
    const float* field = (const float*)d_in[0];
    const float* query = (const float*)d_in[1];
    const float* W_fk  = (const float*)d_in[2];
    const float* b_fk  = (const float*)d_in[3];
    const float* W_fv  = (const float*)d_in[4];
    const float* b_fv  = (const float*)d_in[5];
    const float* W_qk  = (const float*)d_in[6];
    const float* b_qk  = (const float*)d_in[7];
    float* out = (float*)d_out;

    dim3 gproj(LL/256, BB, 3);
    proj_kernel<<<gproj, 256>>>(field, query, W_fk, b_fk, W_fv, b_fv, W_qk, b_qk);

    dim3 gattn(LL/TQ, BB);
    attn_kernel<<<gattn, 256>>>(out);
}

// round 3
// speedup vs baseline: 3.4600x; 3.4600x over previous
#include <cuda_runtime.h>
#include <cuda_bf16.h>
#include <cstdint>

#define BB 4
#define NF 128
#define NK 64
#define NV 64
#define LL 4096
#define TQ 128
#define TL 128
#define NT (LL / TL)

// smem row pitches (bytes): 64 bf16 rows padded to 72 (36 words = 4 mod 32),
// 128 bf16 rows padded to 136 (68 words = 4 mod 32) -> conflict-free frags
#define HQROWB 144
#define FVROWB 272

#define OFF_HQH 0
#define OFF_HQL 18432
#define OFF_FKB 36864          // 2 buffers x (hi 18432 + lo 18432)
#define FKBUFSZ 36864
#define OFF_FVB 110592         // 2 buffers x (hi 17408 + lo 17408)
#define FVBUFSZ 34816
#define OFF_DEN 180224         // float[2][128]
#define SMEM_TOTAL 181248
#define OFF_YS 36864           // reuse fk buffers post-loop: float[128][68]

// bf16 hi/lo projection outputs
__device__ __align__(256) __nv_bfloat16 g_hqh[BB * LL * NK];  // [b][q][k]
__device__ __align__(256) __nv_bfloat16 g_hql[BB * LL * NK];
__device__ __align__(256) __nv_bfloat16 g_fkh[BB * LL * NK];  // [b][l][k]
__device__ __align__(256) __nv_bfloat16 g_fkl[BB * LL * NK];
__device__ __align__(256) __nv_bfloat16 g_fvh[BB * NV * LL];  // [b][v][l]
__device__ __align__(256) __nv_bfloat16 g_fvl[BB * NV * LL];

// ---------------------------------------------------------------------------
__device__ __forceinline__ uint32_t smem_u32(const void* p) {
    uint32_t a;
    asm("{ .reg .u64 t; cvta.to.shared.u64 t, %1; cvt.u32.u64 %0, t; }"
        : "=r"(a) : "l"(p));
    return a;
}
__device__ __forceinline__ void cpasync16(uint32_t dst, const void* src) {
    asm volatile("cp.async.cg.shared.global [%0], [%1], 16;"
                 :: "r"(dst), "l"(src));
}
#define CP_COMMIT() asm volatile("cp.async.commit_group;")
#define CP_WAIT(n)  asm volatile("cp.async.wait_group %0;" :: "n"(n))

__device__ __forceinline__ void mma16816(
    float& d0, float& d1, float& d2, float& d3,
    uint32_t a0, uint32_t a1, uint32_t a2, uint32_t a3,
    uint32_t b0, uint32_t b1)
{
    asm volatile(
        "mma.sync.aligned.m16n8k16.row.col.f32.bf16.bf16.f32 "
        "{%0,%1,%2,%3}, {%4,%5,%6,%7}, {%8,%9}, {%0,%1,%2,%3};"
        : "+f"(d0), "+f"(d1), "+f"(d2), "+f"(d3)
        : "r"(a0), "r"(a1), "r"(a2), "r"(a3), "r"(b0), "r"(b1));
}

// split (x0,x1) -> packed bf16x2 hi and lo (x = hi + lo + O(2^-18 x))
__device__ __forceinline__ void split2(float x0, float x1,
                                       uint32_t& h, uint32_t& l) {
    uint32_t hp;
    asm("cvt.rn.bf16x2.f32 %0, %1, %2;" : "=r"(hp) : "f"(x1), "f"(x0));
    float h0 = __uint_as_float(hp << 16);
    float h1 = __uint_as_float(hp & 0xffff0000u);
    float l0 = x0 - h0, l1 = x1 - h1;
    uint32_t lp;
    asm("cvt.rn.bf16x2.f32 %0, %1, %2;" : "=r"(lp) : "f"(l1), "f"(l0));
    h = hp; l = lp;
}

// ---------------------------------------------------------------------------
// Kernel A: projections -> bf16 hi/lo in MMA-friendly layouts
// z=0: fk [b][l][k]; z=1: fv [b][v][l]; z=2: hq [b][q][k]
// ---------------------------------------------------------------------------
__global__ __launch_bounds__(256) void proj_kernel(
    const float* __restrict__ field, const float* __restrict__ query,
    const float* __restrict__ W_fk, const float* __restrict__ b_fk,
    const float* __restrict__ W_fv, const float* __restrict__ b_fv,
    const float* __restrict__ W_qk, const float* __restrict__ b_qk)
{
    const float *W, *bias, *X;
    switch (blockIdx.z) {
        case 0:  W = W_fk; bias = b_fk; X = field; break;
        case 1:  W = W_fv; bias = b_fv; X = field; break;
        default: W = W_qk; bias = b_qk; X = query; break;
    }
    __shared__ float Ws[NK * NF];
    __shared__ float bs[NK];
    for (int i = threadIdx.x; i < NK * NF; i += 256) Ws[i] = W[i];
    if (threadIdx.x < NK) bs[threadIdx.x] = bias[threadIdx.x];
    __syncthreads();

    const int b = blockIdx.y;
    const int l = blockIdx.x * 256 + threadIdx.x;
    const float* x = X + (size_t)b * NF * LL + l;

    float acc[NK];
    #pragma unroll
    for (int k = 0; k < NK; k++) acc[k] = bs[k];
    #pragma unroll 4
    for (int c = 0; c < NF; c++) {
        float xv = x[(size_t)c * LL];
        #pragma unroll
        for (int k = 0; k < NK; k++) acc[k] = fmaf(Ws[k * NF + c], xv, acc[k]);
    }

    if (blockIdx.z == 1) {
        #pragma unroll
        for (int k = 0; k < NK; k++) {
            __nv_bfloat16 h = __float2bfloat16_rn(acc[k]);
            size_t o = ((size_t)b * NV + k) * LL + l;
            g_fvh[o] = h;
            g_fvl[o] = __float2bfloat16_rn(acc[k] - __bfloat162float(h));
        }
    } else {
        __nv_bfloat16* dh = (blockIdx.z == 0 ? g_fkh : g_hqh) + ((size_t)b * LL + l) * NK;
        __nv_bfloat16* dl = (blockIdx.z == 0 ? g_fkl : g_hql) + ((size_t)b * LL + l) * NK;
        uint32_t hr[32], lr[32];
        #pragma unroll
        for (int k2 = 0; k2 < 32; k2++)
            split2(acc[2 * k2], acc[2 * k2 + 1], hr[k2], lr[k2]);
        #pragma unroll
        for (int i = 0; i < 8; i++) {
            ((uint4*)dh)[i] = ((uint4*)hr)[i];
            ((uint4*)dl)[i] = ((uint4*)lr)[i];
        }
    }
}

// ---------------------------------------------------------------------------
// Kernel B: flash attention with mma.sync bf16 (hi/lo 3-term split).
// CTA = (batch, 128-q tile). 8 warps: wr = warp&3 (q 32-rows), wc = warp>>2
// (l 64-cols). Y accumulated in registers across tiles; w stays in registers.
// ---------------------------------------------------------------------------
__global__ __launch_bounds__(256, 1) void attn_kernel(float* __restrict__ out)
{
    extern __shared__ __align__(16) char sm[];
    const uint32_t sb = smem_u32(sm);

    const int tid = threadIdx.x;
    const int lane = tid & 31, warp = tid >> 5;
    const int gid = lane >> 2, tig = lane & 3;
    const int wr = warp & 3, wc = warp >> 2;
    const int qw = wr * 32;
    const int b = blockIdx.y;
    const int qbase = blockIdx.x * TQ;

    const __nv_bfloat16* hqh_g = g_hqh + ((size_t)b * LL + qbase) * NK;
    const __nv_bfloat16* hql_g = g_hql + ((size_t)b * LL + qbase) * NK;

    // ---- prologue: hq tile + field tile 0 via cp.async ----
    for (int i = tid; i < 1024; i += 256) {
        int row = i >> 3, c = i & 7;
        cpasync16(sb + OFF_HQH + row * HQROWB + c * 16, hqh_g + row * NK + c * 8);
        cpasync16(sb + OFF_HQL + row * HQROWB + c * 16, hql_g + row * NK + c * 8);
    }
    {
        const __nv_bfloat16* fh = g_fkh + (size_t)b * LL * NK;
        const __nv_bfloat16* fl = g_fkl + (size_t)b * LL * NK;
        for (int i = tid; i < 1024; i += 256) {
            int row = i >> 3, c = i & 7;
            cpasync16(sb + OFF_FKB + row * HQROWB + c * 16, fh + row * NK + c * 8);
            cpasync16(sb + OFF_FKB + 18432 + row * HQROWB + c * 16, fl + row * NK + c * 8);
        }
        const __nv_bfloat16* vh = g_fvh + (size_t)b * NV * LL;
        const __nv_bfloat16* vl = g_fvl + (size_t)b * NV * LL;
        for (int i = tid; i < 1024; i += 256) {
            int v = i >> 4, c = i & 15;
            cpasync16(sb + OFF_FVB + v * FVROWB + c * 16, vh + (size_t)v * LL + c * 8);
            cpasync16(sb + OFF_FVB + 17408 + v * FVROWB + c * 16, vl + (size_t)v * LL + c * 8);
        }
    }
    CP_COMMIT();

    float y[2][8][4];
    #pragma unroll
    for (int m = 0; m < 2; m++)
        #pragma unroll
        for (int j = 0; j < 8; j++)
            #pragma unroll
            for (int i = 0; i < 4; i++) y[m][j][i] = 0.f;
    float dnp[4] = {0.f, 0.f, 0.f, 0.f};

    for (int t = 0; t < NT; ++t) {
        if (t + 1 < NT) {
            __syncthreads();  // all warps done reading buffer (t+1)&1
            int buf = (t + 1) & 1;
            const __nv_bfloat16* fh = g_fkh + ((size_t)b * LL + (t + 1) * TL) * NK;
            const __nv_bfloat16* fl = g_fkl + ((size_t)b * LL + (t + 1) * TL) * NK;
            for (int i = tid; i < 1024; i += 256) {
                int row = i >> 3, c = i & 7;
                uint32_t d = sb + OFF_FKB + buf * FKBUFSZ + row * HQROWB + c * 16;
                cpasync16(d, fh + row * NK + c * 8);
                cpasync16(d + 18432, fl + row * NK + c * 8);
            }
            const __nv_bfloat16* vh = g_fvh + (size_t)b * NV * LL + (t + 1) * TL;
            const __nv_bfloat16* vl = g_fvl + (size_t)b * NV * LL + (t + 1) * TL;
            for (int i = tid; i < 1024; i += 256) {
                int v = i >> 4, c = i & 15;
                uint32_t d = sb + OFF_FVB + buf * FVBUFSZ + v * FVROWB + c * 16;
                cpasync16(d, vh + (size_t)v * LL + c * 8);
                cpasync16(d + 17408, vl + (size_t)v * LL + c * 8);
            }
            CP_COMMIT();
            CP_WAIT(1);
        } else {
            CP_WAIT(0);
        }
        __syncthreads();

        const int buf = t & 1;
        const char* fk_h = sm + OFF_FKB + buf * FKBUFSZ;
        const char* fk_l = fk_h + 18432;
        const char* fv_h = sm + OFF_FVB + buf * FVBUFSZ;
        const char* fv_l = fv_h + 17408;

        // ---- MMA1: S[q 32][l 64] per warp, K=64, 3 split terms ----
        float s[2][8][4];
        #pragma unroll
        for (int m = 0; m < 2; m++)
            #pragma unroll
            for (int j = 0; j < 8; j++)
                #pragma unroll
                for (int i = 0; i < 4; i++) s[m][j][i] = 0.f;

        const char* aB[3] = { sm + OFF_HQH, sm + OFF_HQH, sm + OFF_HQL };
        const char* bB[3] = { fk_h, fk_l, fk_h };
        #pragma unroll
        for (int term = 0; term < 3; term++) {
            #pragma unroll
            for (int c = 0; c < 4; c++) {
                uint32_t a[2][4];
                #pragma unroll
                for (int m = 0; m < 2; m++) {
                    const char* r = aB[term] + (qw + m * 16 + gid) * HQROWB + c * 32 + tig * 4;
                    a[m][0] = *(const uint32_t*)(r);
                    a[m][1] = *(const uint32_t*)(r + 8 * HQROWB);
                    a[m][2] = *(const uint32_t*)(r + 16);
                    a[m][3] = *(const uint32_t*)(r + 8 * HQROWB + 16);
                }
                #pragma unroll
                for (int j = 0; j < 8; j++) {
                    const char* rb = bB[term] + (wc * 64 + 8 * j + gid) * HQROWB + c * 32 + tig * 4;
                    uint32_t b0 = *(const uint32_t*)(rb);
                    uint32_t b1 = *(const uint32_t*)(rb + 16);
                    mma16816(s[0][j][0], s[0][j][1], s[0][j][2], s[0][j][3],
                             a[0][0], a[0][1], a[0][2], a[0][3], b0, b1);
                    mma16816(s[1][j][0], s[1][j][1], s[1][j][2], s[1][j][3],
                             a[1][0], a[1][1], a[1][2], a[1][3], b0, b1);
                }
            }
        }

        // ---- epilogue: w = exp(clip(S/8)), denom, pack w as A-fragments ----
        #pragma unroll
        for (int m = 0; m < 2; m++)
            #pragma unroll
            for (int j = 0; j < 8; j++)
                #pragma unroll
                for (int i = 0; i < 4; i++) {
                    float z = s[m][j][i] * 0.125f;
                    z = fminf(fmaxf(z, -30.f), 30.f);
                    float w = __expf(z);
                    s[m][j][i] = w;
                    dnp[m * 2 + (i >> 1)] += w;
                }

        uint32_t wh[2][4][4], wl[2][4][4];
        #pragma unroll
        for (int m = 0; m < 2; m++)
            #pragma unroll
            for (int c = 0; c < 4; c++) {
                split2(s[m][2 * c][0],     s[m][2 * c][1],     wh[m][c][0], wl[m][c][0]);
                split2(s[m][2 * c][2],     s[m][2 * c][3],     wh[m][c][1], wl[m][c][1]);
                split2(s[m][2 * c + 1][0], s[m][2 * c + 1][1], wh[m][c][2], wl[m][c][2]);
                split2(s[m][2 * c + 1][2], s[m][2 * c + 1][3], wh[m][c][3], wl[m][c][3]);
            }

        // ---- MMA2: Y[q 32][v 64] += w[q, l64] * fv[v, l64], 3 terms ----
        const char* b2B[3] = { fv_h, fv_l, fv_h };
        #pragma unroll
        for (int term = 0; term < 3; term++) {
            const uint32_t (*Wf)[4][4] = (term == 2) ? wl : wh;
            #pragma unroll
            for (int c = 0; c < 4; c++) {
                #pragma unroll
                for (int j = 0; j < 8; j++) {
                    const char* rb = b2B[term] + (8 * j + gid) * FVROWB + wc * 128 + c * 32 + tig * 4;
                    uint32_t b0 = *(const uint32_t*)(rb);
                    uint32_t b1 = *(const uint32_t*)(rb + 16);
                    mma16816(y[0][j][0], y[0][j][1], y[0][j][2], y[0][j][3],
                             Wf[0][c][0], Wf[0][c][1], Wf[0][c][2], Wf[0][c][3], b0, b1);
                    mma16816(y[1][j][0], y[1][j][1], y[1][j][2], y[1][j][3],
                             Wf[1][c][0], Wf[1][c][1], Wf[1][c][2], Wf[1][c][3], b0, b1);
                }
            }
        }
    }

    // ---- final reductions ----
    __syncthreads();  // everyone done with fk buffers (ys aliases them)

    #pragma unroll
    for (int k = 0; k < 4; k++) {
        dnp[k] += __shfl_xor_sync(0xffffffffu, dnp[k], 1);
        dnp[k] += __shfl_xor_sync(0xffffffffu, dnp[k], 2);
    }
    float* den = (float*)(sm + OFF_DEN);
    if (tig == 0) {
        #pragma unroll
        for (int m = 0; m < 2; m++) {
            den[wc * 128 + qw + m * 16 + gid]     = dnp[2 * m];
            den[wc * 128 + qw + m * 16 + 8 + gid] = dnp[2 * m + 1];
        }
    }
    float* ysf = (float*)(sm + OFF_YS);  // [128 q][68] (v cols 0..63)
    if (wc == 0) {
        #pragma unroll
        for (int m = 0; m < 2; m++)
            #pragma unroll
            for (int j = 0; j < 8; j++)
                #pragma unroll
                for (int i = 0; i < 4; i++) {
                    int q = qw + m * 16 + gid + (i >> 1) * 8;
                    int v = 8 * j + 2 * tig + (i & 1);
                    ysf[q * 68 + v] = y[m][j][i];
                }
    }
    __syncthreads();
    if (wc == 1) {
        #pragma unroll
        for (int m = 0; m < 2; m++)
            #pragma unroll
            for (int j = 0; j < 8; j++)
                #pragma unroll
                for (int i = 0; i < 4; i++) {
                    int q = qw + m * 16 + gid + (i >> 1) * 8;
                    int v = 8 * j + 2 * tig + (i & 1);
                    ysf[q * 68 + v] += y[m][j][i];
                }
    } else if (tid < 128) {
        float d = den[tid] + den[128 + tid] + 1e-16f;
        den[tid] = 1.0f / d;
    }
    __syncthreads();

    #pragma unroll
    for (int it = 0; it < 32; it++) {
        int idx = tid + it * 256;
        int v = idx >> 7, q = idx & 127;
        out[((size_t)b * NV + v) * LL + qbase + q] = ysf[q * 68 + v] * den[q];
    }
}

// ---------------------------------------------------------------------------
extern "C" void kernel_launch(void* const* d_in, const int* in_sizes, int n_in,
                              void* d_out, int out_size)
{
    const float* field = (const float*)d_in[0];
    const float* query = (const float*)d_in[1];
    const float* W_fk  = (const float*)d_in[2];
    const float* b_fk  = (const float*)d_in[3];
    const float* W_fv  = (const float*)d_in[4];
    const float* b_fv  = (const float*)d_in[5];
    const float* W_qk  = (const float*)d_in[6];
    const float* b_qk  = (const float*)d_in[7];
    float* out = (float*)d_out;

    static int configured = 0;
    if (!configured) {
        cudaFuncSetAttribute(attn_kernel,
                             cudaFuncAttributeMaxDynamicSharedMemorySize,
                             SMEM_TOTAL);
        configured = 1;
    }

    dim3 gproj(LL / 256, BB, 3);
    proj_kernel<<<gproj, 256>>>(field, query, W_fk, b_fk, W_fv, b_fv, W_qk, b_qk);

    dim3 gattn(LL / TQ, BB);  // 32 x 4 = 128 CTAs
    attn_kernel<<<gattn, 256, SMEM_TOTAL>>>(out);
}